// round 5
// baseline (speedup 1.0000x reference)
#include <cuda_runtime.h>
#include <cstdint>

// Problem: out[b,l,g*512+h*64+d] = (x @ Wkv + bkv)[b,l, g*128+64+d]  (softmax over
// size-1 axis == 1, so Q path is dead; output = V replicated over 8 heads/group).
// GEMM: M=16384, K=2048, N=256 (the 4 groups' V columns), tf32 mma.sync.

#define K_DIM    2048
#define KV_COLS  512
#define OUT_COLS 2048

#define BM 128
#define BN 256
#define BK 32
#define NTHREADS 512

#define XS_STRIDE 36            // BK + 4  -> A-frag LDS conflict-free (bank = 4r+c)
#define WS_STRIDE 264           // BN + 8  -> B-frag LDS conflict-free (bank = 8c+r)
#define XS_WORDS (BM * XS_STRIDE)        // 4608
#define WS_WORDS (BK * WS_STRIDE)        // 8448
#define STAGE_WORDS (XS_WORDS + WS_WORDS)
#define SMEM_BYTES (2 * STAGE_WORDS * 4) // 104448

__device__ __forceinline__ uint32_t smem_u32(const void* p) {
    return (uint32_t)__cvta_generic_to_shared(p);
}
__device__ __forceinline__ void cp_async16(uint32_t dst, const void* src) {
    asm volatile("cp.async.cg.shared.global [%0], [%1], 16;" :: "r"(dst), "l"(src));
}
__device__ __forceinline__ void cp_commit() {
    asm volatile("cp.async.commit_group;");
}
template <int N>
__device__ __forceinline__ void cp_wait() {
    asm volatile("cp.async.wait_group %0;" :: "n"(N));
}
__device__ __forceinline__ uint32_t f2tf32(float f) {
    uint32_t r;
    asm("cvt.rna.tf32.f32 %0, %1;" : "=r"(r) : "f"(f));
    return r;
}
__device__ __forceinline__ void mma_tf32(float c[4],
                                         uint32_t a0, uint32_t a1, uint32_t a2, uint32_t a3,
                                         uint32_t b0, uint32_t b1) {
    asm volatile(
        "mma.sync.aligned.m16n8k8.row.col.f32.tf32.tf32.f32 "
        "{%0,%1,%2,%3}, {%4,%5,%6,%7}, {%8,%9}, {%0,%1,%2,%3};"
        : "+f"(c[0]), "+f"(c[1]), "+f"(c[2]), "+f"(c[3])
        : "r"(a0), "r"(a1), "r"(a2), "r"(a3), "r"(b0), "r"(b1));
}

// Load one (BM x BK) X tile and (BK x BN) W_v tile (gathered from the 4 groups'
// V column blocks of Wkv) into a stage via cp.async.
__device__ __forceinline__ void load_tile(const float* __restrict__ x,
                                          const float* __restrict__ Wkv,
                                          int block_m, int kk,
                                          float* stage, int tid) {
    uint32_t xb = smem_u32(stage);
    uint32_t wb = smem_u32(stage + XS_WORDS);
    // X: 128 rows x 32 floats = 1024 x 16B chunks, 2 per thread
    #pragma unroll
    for (int i = 0; i < 2; i++) {
        int idx = tid + i * NTHREADS;
        int row = idx >> 3;                 // 0..127
        int c4  = (idx & 7) << 2;           // 0..28
        cp_async16(xb + (uint32_t)(row * XS_STRIDE + c4) * 4u,
                   x + (size_t)(block_m + row) * K_DIM + kk + c4);
    }
    // W: 32 rows x 256 floats = 2048 x 16B chunks, 4 per thread.
    // smem col n (0..255) <- Wkv col (n>>6)*128 + 64 + (n&63); each 16B chunk
    // stays inside one 64-col group block, so this maps chunk-contiguously.
    #pragma unroll
    for (int i = 0; i < 4; i++) {
        int idx = tid + i * NTHREADS;
        int row = idx >> 6;                 // 0..31
        int c4  = (idx & 63) << 2;          // 0..252
        int gcol = ((c4 >> 6) * 128) + 64 + (c4 & 63);
        cp_async16(wb + (uint32_t)(row * WS_STRIDE + c4) * 4u,
                   Wkv + (size_t)(kk + row) * KV_COLS + gcol);
    }
    cp_commit();
}

__global__ void __launch_bounds__(NTHREADS, 1)
gqa_v_kernel(const float* __restrict__ x,
             const float* __restrict__ Wkv,
             const float* __restrict__ bkv,
             float* __restrict__ out) {
    extern __shared__ float smem[];

    const int tid    = threadIdx.x;
    const int lane   = tid & 31;
    const int warp   = tid >> 5;
    const int warp_m = warp >> 2;              // 0..3  (rows: 32 each)
    const int warp_n = warp & 3;               // 0..3  (cols: 64 each == one group)
    const int block_m = blockIdx.x * BM;

    float acc[2][8][4];
    #pragma unroll
    for (int mt = 0; mt < 2; mt++)
        #pragma unroll
        for (int nt = 0; nt < 8; nt++)
            #pragma unroll
            for (int i = 0; i < 4; i++) acc[mt][nt][i] = 0.f;

    const int NT = K_DIM / BK;                 // 64 stages

    load_tile(x, Wkv, block_m, 0, smem, tid);

    for (int t = 0; t < NT; t++) {
        const int s = t & 1;
        if (t + 1 < NT) {
            load_tile(x, Wkv, block_m, (t + 1) * BK,
                      smem + (s ^ 1) * STAGE_WORDS, tid);
            cp_wait<1>();
        } else {
            cp_wait<0>();
        }
        __syncthreads();

        const float* X = smem + s * STAGE_WORDS;
        const float* W = X + XS_WORDS;

        #pragma unroll
        for (int k8 = 0; k8 < BK; k8 += 8) {
            uint32_t a[2][4], b[8][2];
            #pragma unroll
            for (int mt = 0; mt < 2; mt++) {
                const float* p = X + (warp_m * 32 + mt * 16 + (lane >> 2)) * XS_STRIDE
                                   + k8 + (lane & 3);
                a[mt][0] = f2tf32(p[0]);
                a[mt][1] = f2tf32(p[8 * XS_STRIDE]);
                a[mt][2] = f2tf32(p[4]);
                a[mt][3] = f2tf32(p[8 * XS_STRIDE + 4]);
            }
            #pragma unroll
            for (int nt = 0; nt < 8; nt++) {
                const float* p = W + (k8 + (lane & 3)) * WS_STRIDE
                                   + warp_n * 64 + nt * 8 + (lane >> 2);
                b[nt][0] = f2tf32(p[0]);
                b[nt][1] = f2tf32(p[4 * WS_STRIDE]);
            }
            #pragma unroll
            for (int mt = 0; mt < 2; mt++)
                #pragma unroll
                for (int nt = 0; nt < 8; nt++)
                    mma_tf32(acc[mt][nt],
                             a[mt][0], a[mt][1], a[mt][2], a[mt][3],
                             b[nt][0], b[nt][1]);
        }
        __syncthreads();
    }

    // Epilogue: bias + replicate each V value across the 8 heads of its group.
    // warp_n IS the group. out[r, warp_n*512 + h*64 + d] = V[r, warp_n*64 + d]
    #pragma unroll
    for (int nt = 0; nt < 8; nt++) {
        const int d  = nt * 8 + (lane & 3) * 2;                 // 0..62 within group
        const float b0 = bkv[warp_n * 128 + 64 + d];
        const float b1 = bkv[warp_n * 128 + 64 + d + 1];
        #pragma unroll
        for (int mt = 0; mt < 2; mt++) {
            float2 v0 = make_float2(acc[mt][nt][0] + b0, acc[mt][nt][1] + b1);
            float2 v1 = make_float2(acc[mt][nt][2] + b0, acc[mt][nt][3] + b1);
            const int r0 = block_m + warp_m * 32 + mt * 16 + (lane >> 2);
            size_t base0 = (size_t)r0 * OUT_COLS + warp_n * 512 + d;
            size_t base1 = base0 + (size_t)8 * OUT_COLS;
            #pragma unroll
            for (int h = 0; h < 8; h++) {
                *reinterpret_cast<float2*>(out + base0 + h * 64) = v0;
                *reinterpret_cast<float2*>(out + base1 + h * 64) = v1;
            }
        }
    }
}

extern "C" void kernel_launch(void* const* d_in, const int* in_sizes, int n_in,
                              void* d_out, int out_size) {
    const float* x   = (const float*)d_in[0];
    const float* Wkv = (const float*)d_in[3];
    const float* bkv = (const float*)d_in[4];
    float* out = (float*)d_out;

    static bool attr_set = false;
    if (!attr_set) {
        cudaFuncSetAttribute(gqa_v_kernel,
                             cudaFuncAttributeMaxDynamicSharedMemorySize, SMEM_BYTES);
        attr_set = true;
    }

    const int M = in_sizes[0] / K_DIM;     // 16384
    dim3 grid(M / BM);                     // 128 blocks, single wave on 148 SMs
    gqa_v_kernel<<<grid, NTHREADS, SMEM_BYTES>>>(x, Wkv, bkv, out);
}

// round 6
// speedup vs baseline: 1.0306x; 1.0306x over previous
#include <cuda_runtime.h>
#include <cstdint>

// Problem: out[b,l,g*512+h*64+d] = (x @ Wkv + bkv)[b,l, g*128+64+d]  (softmax over
// size-1 axis == 1, so Q path is dead; output = V replicated over 8 heads/group).
// GEMM: M=16384, K=2048, N=256 (the 4 groups' V columns), tf32 mma.sync.

#define K_DIM    2048
#define KV_COLS  512
#define OUT_COLS 2048

#define BM 128
#define BN 256
#define BK 32
#define NTHREADS 512

#define XS_STRIDE 36            // BK + 4  -> A-frag LDS conflict-free (bank = 4r+c)
#define WS_STRIDE 264           // BN + 8  -> B-frag LDS conflict-free (bank = 8c+r)
#define XS_WORDS (BM * XS_STRIDE)        // 4608
#define WS_WORDS (BK * WS_STRIDE)        // 8448
#define STAGE_WORDS (XS_WORDS + WS_WORDS)
#define SMEM_BYTES (2 * STAGE_WORDS * 4) // 104448

__device__ __forceinline__ uint32_t smem_u32(const void* p) {
    return (uint32_t)__cvta_generic_to_shared(p);
}
__device__ __forceinline__ void cp_async16(uint32_t dst, const void* src) {
    asm volatile("cp.async.cg.shared.global [%0], [%1], 16;" :: "r"(dst), "l"(src));
}
__device__ __forceinline__ void cp_commit() {
    asm volatile("cp.async.commit_group;");
}
template <int N>
__device__ __forceinline__ void cp_wait() {
    asm volatile("cp.async.wait_group %0;" :: "n"(N));
}
__device__ __forceinline__ uint32_t f2tf32(float f) {
    uint32_t r;
    asm("cvt.rna.tf32.f32 %0, %1;" : "=r"(r) : "f"(f));
    return r;
}
__device__ __forceinline__ void mma_tf32(float c[4],
                                         uint32_t a0, uint32_t a1, uint32_t a2, uint32_t a3,
                                         uint32_t b0, uint32_t b1) {
    asm volatile(
        "mma.sync.aligned.m16n8k8.row.col.f32.tf32.tf32.f32 "
        "{%0,%1,%2,%3}, {%4,%5,%6,%7}, {%8,%9}, {%0,%1,%2,%3};"
        : "+f"(c[0]), "+f"(c[1]), "+f"(c[2]), "+f"(c[3])
        : "r"(a0), "r"(a1), "r"(a2), "r"(a3), "r"(b0), "r"(b1));
}

// Load one (BM x BK) X tile and (BK x BN) W_v tile (gathered from the 4 groups'
// V column blocks of Wkv) into a stage via cp.async.
__device__ __forceinline__ void load_tile(const float* __restrict__ x,
                                          const float* __restrict__ Wkv,
                                          int block_m, int kk,
                                          float* stage, int tid) {
    uint32_t xb = smem_u32(stage);
    uint32_t wb = smem_u32(stage + XS_WORDS);
    // X: 128 rows x 32 floats = 1024 x 16B chunks, 2 per thread
    #pragma unroll
    for (int i = 0; i < 2; i++) {
        int idx = tid + i * NTHREADS;
        int row = idx >> 3;                 // 0..127
        int c4  = (idx & 7) << 2;           // 0..28
        cp_async16(xb + (uint32_t)(row * XS_STRIDE + c4) * 4u,
                   x + (size_t)(block_m + row) * K_DIM + kk + c4);
    }
    // W: 32 rows x 256 floats = 2048 x 16B chunks, 4 per thread.
    // smem col n (0..255) <- Wkv col (n>>6)*128 + 64 + (n&63); each 16B chunk
    // stays inside one 64-col group block, so this maps chunk-contiguously.
    #pragma unroll
    for (int i = 0; i < 4; i++) {
        int idx = tid + i * NTHREADS;
        int row = idx >> 6;                 // 0..31
        int c4  = (idx & 63) << 2;          // 0..252
        int gcol = ((c4 >> 6) * 128) + 64 + (c4 & 63);
        cp_async16(wb + (uint32_t)(row * WS_STRIDE + c4) * 4u,
                   Wkv + (size_t)(kk + row) * KV_COLS + gcol);
    }
    cp_commit();
}

__global__ void __launch_bounds__(NTHREADS, 1)
gqa_v_kernel(const float* __restrict__ x,
             const float* __restrict__ Wkv,
             const float* __restrict__ bkv,
             float* __restrict__ out) {
    extern __shared__ float smem[];

    const int tid    = threadIdx.x;
    const int lane   = tid & 31;
    const int warp   = tid >> 5;
    const int warp_m = warp >> 2;              // 0..3  (rows: 32 each)
    const int warp_n = warp & 3;               // 0..3  (cols: 64 each == one group)
    const int block_m = blockIdx.x * BM;

    float acc[2][8][4];
    #pragma unroll
    for (int mt = 0; mt < 2; mt++)
        #pragma unroll
        for (int nt = 0; nt < 8; nt++)
            #pragma unroll
            for (int i = 0; i < 4; i++) acc[mt][nt][i] = 0.f;

    const int NT = K_DIM / BK;                 // 64 stages

    load_tile(x, Wkv, block_m, 0, smem, tid);

    for (int t = 0; t < NT; t++) {
        const int s = t & 1;
        if (t + 1 < NT) {
            load_tile(x, Wkv, block_m, (t + 1) * BK,
                      smem + (s ^ 1) * STAGE_WORDS, tid);
            cp_wait<1>();
        } else {
            cp_wait<0>();
        }
        __syncthreads();

        const float* X = smem + s * STAGE_WORDS;
        const float* W = X + XS_WORDS;

        #pragma unroll
        for (int k8 = 0; k8 < BK; k8 += 8) {
            uint32_t a[2][4], b[8][2];
            #pragma unroll
            for (int mt = 0; mt < 2; mt++) {
                const float* p = X + (warp_m * 32 + mt * 16 + (lane >> 2)) * XS_STRIDE
                                   + k8 + (lane & 3);
                a[mt][0] = f2tf32(p[0]);
                a[mt][1] = f2tf32(p[8 * XS_STRIDE]);
                a[mt][2] = f2tf32(p[4]);
                a[mt][3] = f2tf32(p[8 * XS_STRIDE + 4]);
            }
            #pragma unroll
            for (int nt = 0; nt < 8; nt++) {
                const float* p = W + (k8 + (lane & 3)) * WS_STRIDE
                                   + warp_n * 64 + nt * 8 + (lane >> 2);
                b[nt][0] = f2tf32(p[0]);
                b[nt][1] = f2tf32(p[4 * WS_STRIDE]);
            }
            #pragma unroll
            for (int mt = 0; mt < 2; mt++)
                #pragma unroll
                for (int nt = 0; nt < 8; nt++)
                    mma_tf32(acc[mt][nt],
                             a[mt][0], a[mt][1], a[mt][2], a[mt][3],
                             b[nt][0], b[nt][1]);
        }
        __syncthreads();
    }

    // Epilogue: bias + replicate each V value across the 8 heads of its group.
    // warp_n IS the group. out[r, warp_n*512 + h*64 + d] = V[r, warp_n*64 + d]
    #pragma unroll
    for (int nt = 0; nt < 8; nt++) {
        const int d  = nt * 8 + (lane & 3) * 2;                 // 0..62 within group
        const float b0 = bkv[warp_n * 128 + 64 + d];
        const float b1 = bkv[warp_n * 128 + 64 + d + 1];
        #pragma unroll
        for (int mt = 0; mt < 2; mt++) {
            float2 v0 = make_float2(acc[mt][nt][0] + b0, acc[mt][nt][1] + b1);
            float2 v1 = make_float2(acc[mt][nt][2] + b0, acc[mt][nt][3] + b1);
            const int r0 = block_m + warp_m * 32 + mt * 16 + (lane >> 2);
            size_t base0 = (size_t)r0 * OUT_COLS + warp_n * 512 + d;
            size_t base1 = base0 + (size_t)8 * OUT_COLS;
            #pragma unroll
            for (int h = 0; h < 8; h++) {
                *reinterpret_cast<float2*>(out + base0 + h * 64) = v0;
                *reinterpret_cast<float2*>(out + base1 + h * 64) = v1;
            }
        }
    }
}

extern "C" void kernel_launch(void* const* d_in, const int* in_sizes, int n_in,
                              void* d_out, int out_size) {
    const float* x   = (const float*)d_in[0];
    const float* Wkv = (const float*)d_in[3];
    const float* bkv = (const float*)d_in[4];
    float* out = (float*)d_out;

    static bool attr_set = false;
    if (!attr_set) {
        cudaFuncSetAttribute(gqa_v_kernel,
                             cudaFuncAttributeMaxDynamicSharedMemorySize, SMEM_BYTES);
        attr_set = true;
    }

    const int M = in_sizes[0] / K_DIM;     // 16384
    dim3 grid(M / BM);                     // 128 blocks, single wave on 148 SMs
    gqa_v_kernel<<<grid, NTHREADS, SMEM_BYTES>>>(x, Wkv, bkv, out);
}